// round 2
// baseline (speedup 1.0000x reference)
#include <cuda_runtime.h>
#include <cuda_bf16.h>
#include <math_constants.h>

// ---------------------------------------------------------------------------
// MiTA Attention: B=8, N=1025 (32x32 grid + cls at END), C=1024, H=16, d=64,
// M=25 experts (5x5 adaptive pool of q), K=25 selected keys per expert.
// Pipeline:
//   1) qkv = x @ Wqkv                       (GEMM 8200x1024x3072)
//   2) router = adaptive-pool(q spatial)    (200 x 1024 tiny)
//   3) r_logits[b,h,m,n] = r.k ; gate[b,h,n,m] = r.q
//   4) per (b,h,m): top-25 of r_logits row + softmax(row*scale) in place
//   5) agent_value[b,h,m,:] = probs @ v
//   6) per query: expert = argmax_m gate; merged softmax over [25 gate | 25 moba]
//      out = w_a @ agent_value + w_m . v_sel
//   7) out @ Wproj + bproj                  (GEMM 8200x1024x1024)
// ---------------------------------------------------------------------------

#define BATCH 8
#define NTOK 1025
#define CDIM 1024
#define HEADS 16
#define HDIM 64
#define MEXP 25
#define KSEL 25
#define GRID 32
#define POOLN 5
#define SCALE 0.125f
#define MROWS (BATCH * NTOK)       // 8200
#define BH (BATCH * HEADS)         // 128

// ---------------- scratch (global device arrays; no allocation) ------------
__device__ float g_qkv[BATCH * NTOK * 3 * CDIM];          // 100.8 MB
__device__ float g_router[BATCH * MEXP * CDIM];           // 0.8 MB
__device__ float g_rlog[BH * MEXP * NTOK];                // logits -> probs
__device__ float g_gate[BH * NTOK * MEXP];                // [bh][n][m]
__device__ int   g_topk[BH * MEXP * KSEL];
__device__ float g_agentv[BH * MEXP * HDIM];
__device__ float g_attn[BATCH * NTOK * CDIM];             // 33.6 MB

// ---------------------------------------------------------------------------
// GEMM: C[M,N] = A[M,K] @ B[K,N] (+ bias). BM=BN=64, BK=16, 256 thr, 4x4 micro
// ---------------------------------------------------------------------------
__global__ __launch_bounds__(256) void gemm_kernel(
    const float* __restrict__ A, const float* __restrict__ B,
    const float* __restrict__ bias, float* __restrict__ C,
    int Mrows, int Kdim, int Ncols)
{
    __shared__ float As[16][68];   // transposed: As[k][m], padded for alignment
    __shared__ float Bs[16][64];

    const int tid = threadIdx.x;
    const int tm = tid >> 4;          // 0..15
    const int tn = tid & 15;          // 0..15
    const int rowBase = blockIdx.y * 64;
    const int colBase = blockIdx.x * 64;

    // A staging: thread -> (row ar, float4 col ac4)
    const int ar  = tid >> 2;         // 0..63
    const int ac4 = (tid & 3) * 4;    // 0,4,8,12
    // B staging: thread -> (k-row br, float4 col bc4)
    const int br  = tid >> 4;         // 0..15
    const int bc4 = (tid & 15) * 4;

    const bool aValid = (rowBase + ar) < Mrows;
    const float* Aptr = A + (size_t)(rowBase + ar) * Kdim + ac4;
    const float* Bptr = B + (size_t)br * Ncols + colBase + bc4;

    float acc[4][4];
    #pragma unroll
    for (int i = 0; i < 4; i++)
        #pragma unroll
        for (int j = 0; j < 4; j++) acc[i][j] = 0.f;

    for (int kt = 0; kt < Kdim; kt += 16) {
        float4 av = aValid ? *(const float4*)(Aptr + kt) : make_float4(0, 0, 0, 0);
        float4 bv = *(const float4*)(Bptr + (size_t)kt * Ncols);
        As[ac4 + 0][ar] = av.x;
        As[ac4 + 1][ar] = av.y;
        As[ac4 + 2][ar] = av.z;
        As[ac4 + 3][ar] = av.w;
        *(float4*)&Bs[br][bc4] = bv;
        __syncthreads();
        #pragma unroll
        for (int k = 0; k < 16; k++) {
            float4 a = *(const float4*)&As[k][tm * 4];
            float4 b = *(const float4*)&Bs[k][tn * 4];
            acc[0][0] += a.x * b.x; acc[0][1] += a.x * b.y; acc[0][2] += a.x * b.z; acc[0][3] += a.x * b.w;
            acc[1][0] += a.y * b.x; acc[1][1] += a.y * b.y; acc[1][2] += a.y * b.z; acc[1][3] += a.y * b.w;
            acc[2][0] += a.z * b.x; acc[2][1] += a.z * b.y; acc[2][2] += a.z * b.z; acc[2][3] += a.z * b.w;
            acc[3][0] += a.w * b.x; acc[3][1] += a.w * b.y; acc[3][2] += a.w * b.z; acc[3][3] += a.w * b.w;
        }
        __syncthreads();
    }

    #pragma unroll
    for (int i = 0; i < 4; i++) {
        int row = rowBase + tm * 4 + i;
        if (row < Mrows) {
            #pragma unroll
            for (int j = 0; j < 4; j++) {
                int col = colBase + tn * 4 + j;
                float v = acc[i][j];
                if (bias) v += bias[col];
                C[(size_t)row * Ncols + col] = v;
            }
        }
    }
}

// ---------------------------------------------------------------------------
// Router adaptive-pool: router[b,m,c] = mean over window of q[b, h*32+w, c]
// ---------------------------------------------------------------------------
__global__ void router_pool_kernel()
{
    int blk = blockIdx.x;            // b*25 + m
    int b = blk / MEXP, m = blk % MEXP;
    int p = m / POOLN, q = m % POOLN;
    int hs = (p * GRID) / POOLN, he = ((p + 1) * GRID + POOLN - 1) / POOLN;
    int ws = (q * GRID) / POOLN, we = ((q + 1) * GRID + POOLN - 1) / POOLN;
    float inv = 1.0f / (float)((he - hs) * (we - ws));

    for (int c = threadIdx.x; c < CDIM; c += blockDim.x) {
        float s = 0.f;
        for (int h = hs; h < he; h++)
            for (int w = ws; w < we; w++)
                s += g_qkv[((size_t)(b * NTOK + h * GRID + w)) * (3 * CDIM) + c];
        g_router[(size_t)blk * CDIM + c] = s * inv;
    }
}

// ---------------------------------------------------------------------------
// r_logits[b,h,m,n] = sum_d r[m,d]*k[n,d] ; gate[b,h,n,m] = sum_d r[m,d]*q[n,d]
// grid: (ntile=5, bh=128), 256 threads, thread-per-column.
// ---------------------------------------------------------------------------
__global__ __launch_bounds__(256) void logits_kernel()
{
    __shared__ float r_s[MEXP][HDIM];
    int bh = blockIdx.y;
    int b = bh / HEADS, h = bh % HEADS;

    for (int e = threadIdx.x; e < MEXP * HDIM; e += 256) {
        int m = e / HDIM, d = e % HDIM;
        r_s[m][d] = g_router[((size_t)(b * MEXP + m)) * CDIM + h * HDIM + d];
    }
    __syncthreads();

    int n = blockIdx.x * 256 + threadIdx.x;
    if (n >= NTOK) return;

    const float* base = &g_qkv[(size_t)(b * NTOK + n) * (3 * CDIM) + h * HDIM];
    float acck[MEXP], accq[MEXP];
    #pragma unroll
    for (int m = 0; m < MEXP; m++) { acck[m] = 0.f; accq[m] = 0.f; }

    for (int d = 0; d < HDIM; d++) {
        float qv = base[d];
        float kv = base[CDIM + d];
        #pragma unroll
        for (int m = 0; m < MEXP; m++) {
            float r = r_s[m][d];
            acck[m] += r * kv;
            accq[m] += r * qv;
        }
    }
    #pragma unroll
    for (int m = 0; m < MEXP; m++) {
        g_rlog[((size_t)(bh * MEXP + m)) * NTOK + n] = acck[m];
        g_gate[((size_t)(bh * NTOK + n)) * MEXP + m] = accq[m];
    }
}

// ---------------------------------------------------------------------------
// Per (b,h,m) row: top-25 indices, then softmax(row * SCALE) in-place.
// ---------------------------------------------------------------------------
__global__ __launch_bounds__(256) void softmax_topk_kernel()
{
    __shared__ float sv[256];
    __shared__ int   si[256];
    __shared__ float selv[KSEL];
    __shared__ int   seli[KSEL];
    __shared__ float s_inv;

    int row = blockIdx.x;             // bh*25 + m
    float* r = &g_rlog[(size_t)row * NTOK];
    int tid = threadIdx.x;

    // iterative top-25 (mark selected with -inf, restore after)
    for (int it = 0; it < KSEL; it++) {
        float bv = -CUDART_INF_F; int bi = -1;
        for (int n = tid; n < NTOK; n += 256) {
            float v = r[n];
            if (v > bv || (v == bv && n < bi)) { bv = v; bi = n; }
        }
        sv[tid] = bv; si[tid] = bi;
        __syncthreads();
        for (int s = 128; s > 0; s >>= 1) {
            if (tid < s) {
                float ov = sv[tid + s]; int oi = si[tid + s];
                if (ov > sv[tid] || (ov == sv[tid] && oi < si[tid])) {
                    sv[tid] = ov; si[tid] = oi;
                }
            }
            __syncthreads();
        }
        if (tid == 0) {
            selv[it] = sv[0]; seli[it] = si[0];
            r[si[0]] = -CUDART_INF_F;
        }
        __syncthreads();
    }
    // restore values, record topk
    if (tid < KSEL) {
        r[seli[tid]] = selv[tid];
        g_topk[(size_t)row * KSEL + tid] = seli[tid];
    }
    __syncthreads();

    // softmax: global max is selv[0]
    float mx = selv[0];
    float psum = 0.f;
    for (int n = tid; n < NTOK; n += 256) {
        float e = __expf((r[n] - mx) * SCALE);
        r[n] = e;
        psum += e;
    }
    sv[tid] = psum;
    __syncthreads();
    for (int s = 128; s > 0; s >>= 1) {
        if (tid < s) sv[tid] += sv[tid + s];
        __syncthreads();
    }
    if (tid == 0) s_inv = 1.0f / sv[0];
    __syncthreads();
    float inv = s_inv;
    for (int n = tid; n < NTOK; n += 256) r[n] *= inv;
}

// ---------------------------------------------------------------------------
// agent_value[b,h,m,d] = sum_n probs[m,n] * v[n,d].  One block per (b,h).
// ---------------------------------------------------------------------------
__global__ __launch_bounds__(256) void agent_value_kernel()
{
    __shared__ float p_s[MEXP][32];
    __shared__ float v_s[32][HDIM];
    int bh = blockIdx.x;
    int b = bh / HEADS, h = bh % HEADS;
    int tid = threadIdx.x;

    float acc[7];
    #pragma unroll
    for (int i = 0; i < 7; i++) acc[i] = 0.f;

    for (int t0 = 0; t0 < NTOK; t0 += 32) {
        for (int e = tid; e < MEXP * 32; e += 256) {
            int m = e / 32, n = e % 32;
            p_s[m][n] = (t0 + n < NTOK)
                ? g_rlog[((size_t)(bh * MEXP + m)) * NTOK + t0 + n] : 0.f;
        }
        for (int e = tid; e < 32 * HDIM; e += 256) {
            int n = e / HDIM, d = e % HDIM;
            v_s[n][d] = (t0 + n < NTOK)
                ? g_qkv[(size_t)(b * NTOK + t0 + n) * (3 * CDIM) + 2 * CDIM + h * HDIM + d]
                : 0.f;
        }
        __syncthreads();
        for (int n = 0; n < 32; n++) {
            #pragma unroll
            for (int i = 0; i < 7; i++) {
                int pidx = tid + 256 * i;
                if (pidx < MEXP * HDIM) {
                    int m = pidx >> 6, d = pidx & 63;
                    acc[i] += p_s[m][n] * v_s[n][d];
                }
            }
        }
        __syncthreads();
    }
    #pragma unroll
    for (int i = 0; i < 7; i++) {
        int pidx = tid + 256 * i;
        if (pidx < MEXP * HDIM)
            g_agentv[(size_t)bh * MEXP * HDIM + pidx] = acc[i];
    }
}

// ---------------------------------------------------------------------------
// Final per-query mixed attention. Block = (b,h, 16 queries), 256 threads.
// ---------------------------------------------------------------------------
#define TQ 16
__global__ __launch_bounds__(256) void attn_kernel()
{
    __shared__ float ag_s[MEXP][HDIM];     // agent values
    __shared__ float q_s[TQ][HDIM];
    __shared__ float w_s[TQ][65];          // 50 logits/weights, padded
    __shared__ int   sel_s[TQ][KSEL];

    int bh = blockIdx.y;
    int b = bh / HEADS, h = bh % HEADS;
    int n0 = blockIdx.x * TQ;
    int tid = threadIdx.x;

    for (int e = tid; e < MEXP * HDIM; e += 256)
        ((float*)ag_s)[e] = g_agentv[(size_t)bh * MEXP * HDIM + e];
    for (int e = tid; e < TQ * HDIM; e += 256) {
        int qi = e / HDIM, d = e % HDIM;
        int n = n0 + qi;
        q_s[qi][d] = (n < NTOK)
            ? g_qkv[(size_t)(b * NTOK + n) * (3 * CDIM) + h * HDIM + d] : 0.f;
    }
    __syncthreads();

    // per-query gate logits + expert argmax + selected key list
    if (tid < TQ && n0 + tid < NTOK) {
        const float* g = &g_gate[((size_t)(bh * NTOK + n0 + tid)) * MEXP];
        float best = -CUDART_INF_F; int ei = 0;
        #pragma unroll
        for (int m = 0; m < MEXP; m++) {
            float v = g[m];
            w_s[tid][m] = v * SCALE;
            if (v > best) { best = v; ei = m; }
        }
        const int* tk = &g_topk[((size_t)(bh * MEXP + ei)) * KSEL];
        #pragma unroll
        for (int k = 0; k < KSEL; k++) sel_s[tid][k] = tk[k];
    }
    __syncthreads();

    // moba logits: warp-per-task, lane-parallel dot over d
    int warp = tid >> 5, lane = tid & 31;
    for (int task = warp; task < TQ * KSEL; task += 8) {
        int qi = task / KSEL, k = task % KSEL;
        if (n0 + qi < NTOK) {
            int key = sel_s[qi][k];
            const float2* kp = (const float2*)
                &g_qkv[(size_t)(b * NTOK + key) * (3 * CDIM) + CDIM + h * HDIM];
            float2 kv = kp[lane];
            float2 qv = *(const float2*)&q_s[qi][2 * lane];
            float s = qv.x * kv.x + qv.y * kv.y;
            #pragma unroll
            for (int off = 16; off > 0; off >>= 1)
                s += __shfl_xor_sync(0xFFFFFFFFu, s, off);
            if (lane == 0) w_s[qi][MEXP + k] = s * SCALE;
        }
    }
    __syncthreads();

    // merged softmax over 50 logits (serial per query; 16 threads)
    if (tid < TQ && n0 + tid < NTOK) {
        float mx = -CUDART_INF_F;
        #pragma unroll
        for (int j = 0; j < MEXP + KSEL; j++) mx = fmaxf(mx, w_s[tid][j]);
        float sum = 0.f;
        #pragma unroll
        for (int j = 0; j < MEXP + KSEL; j++) {
            float e = __expf(w_s[tid][j] - mx);
            w_s[tid][j] = e;
            sum += e;
        }
        float inv = 1.0f / sum;
        #pragma unroll
        for (int j = 0; j < MEXP + KSEL; j++) w_s[tid][j] *= inv;
    }
    __syncthreads();

    // output: out[qi][d] = w_a @ agent + w_m . v_sel
    int d = tid & 63;
    #pragma unroll
    for (int i = 0; i < 4; i++) {
        int qi = (tid >> 6) + i * 4;
        int n = n0 + qi;
        if (n < NTOK) {
            float o = 0.f;
            #pragma unroll
            for (int m = 0; m < MEXP; m++) o += w_s[qi][m] * ag_s[m][d];
            #pragma unroll
            for (int k = 0; k < KSEL; k++) {
                int key = sel_s[qi][k];
                o += w_s[qi][MEXP + k] *
                     g_qkv[(size_t)(b * NTOK + key) * (3 * CDIM) + 2 * CDIM + h * HDIM + d];
            }
            g_attn[(size_t)(b * NTOK + n) * CDIM + h * HDIM + d] = o;
        }
    }
}

// ---------------------------------------------------------------------------
extern "C" void kernel_launch(void* const* d_in, const int* in_sizes, int n_in,
                              void* d_out, int out_size)
{
    const float* x     = (const float*)d_in[0];
    const float* Wqkv  = (const float*)d_in[1];
    const float* Wproj = (const float*)d_in[2];
    const float* bproj = (const float*)d_in[3];
    float* out = (float*)d_out;

    float* qkv;   cudaGetSymbolAddress((void**)&qkv,   g_qkv);
    float* attn;  cudaGetSymbolAddress((void**)&attn,  g_attn);

    // 1) qkv projection
    {
        dim3 grid(3 * CDIM / 64, (MROWS + 63) / 64);
        gemm_kernel<<<grid, 256>>>(x, Wqkv, nullptr, qkv, MROWS, CDIM, 3 * CDIM);
    }
    // 2) router pooling
    router_pool_kernel<<<BATCH * MEXP, 256>>>();
    // 3) router-key and router-query logits
    {
        dim3 grid((NTOK + 255) / 256, BH);
        logits_kernel<<<grid, 256>>>();
    }
    // 4) top-k + softmax per router row
    softmax_topk_kernel<<<BH * MEXP, 256>>>();
    // 5) agent values
    agent_value_kernel<<<BH, 256>>>();
    // 6) mixed attention
    {
        dim3 grid((NTOK + TQ - 1) / TQ, BH);
        attn_kernel<<<grid, 256>>>();
    }
    // 7) output projection
    {
        dim3 grid(CDIM / 64, (MROWS + 63) / 64);
        gemm_kernel<<<grid, 256>>>(attn, Wproj, bproj, out, MROWS, CDIM, CDIM);
    }
}

// round 8
// speedup vs baseline: 1.5805x; 1.5805x over previous
#include <cuda_runtime.h>
#include <cuda_bf16.h>
#include <math_constants.h>
#include <cstdint>

// ---------------------------------------------------------------------------
// MiTA Attention. compute_103 PTX target (no tcgen05) -> mma.sync HMMA bf16.
// q/k (decision-critical) via bf16x6 split (err ~1e-7); v & proj via bf16x3
// (err ~1e-5, continuous). Split folded into K so one GEMM kernel serves all.
// ---------------------------------------------------------------------------

#define BATCH 8
#define NTOK 1025
#define CDIM 1024
#define HEADS 16
#define HDIM 64
#define MEXP 25
#define KSEL 25
#define GRID 32
#define POOLN 5
#define SCALE 0.125f
#define MROWS (BATCH * NTOK)       // 8200
#define BH (BATCH * HEADS)         // 128
#define K6 (6 * CDIM)              // 6144
#define KT3 (3 * CDIM)             // 3072

// ---------------- scratch ----------------
__device__ float g_qkv[BATCH * NTOK * 3 * CDIM];
__device__ float g_router[BATCH * MEXP * CDIM];
__device__ float g_rlog[BH * MEXP * NTOK];
__device__ float g_gate[BH * NTOK * MEXP];
__device__ int   g_topk[BH * MEXP * KSEL];
__device__ float g_agentv[BH * MEXP * HDIM];
__device__ float g_attn[BATCH * NTOK * CDIM];
__device__ __nv_bfloat16 g_a6[MROWS * K6];        // A'6 for GEMM1a; reused as A'3 later
__device__ __nv_bfloat16 g_b6qk[2 * CDIM * K6];
__device__ __nv_bfloat16 g_b3v[CDIM * KT3];
__device__ __nv_bfloat16 g_b3p[CDIM * KT3];

// ======================= helpers ===========================================
__device__ __forceinline__ uint32_t smem_u32(const void* p) {
    uint32_t a;
    asm("{ .reg .u64 t; cvta.to.shared.u64 t, %1; cvt.u32.u64 %0, t; }" : "=r"(a) : "l"(p));
    return a;
}
#define CP16(dst, src, nbytes) \
    asm volatile("cp.async.cg.shared.global [%0], [%1], 16, %2;" \
        :: "r"(dst), "l"(src), "r"(nbytes) : "memory")

__device__ __forceinline__ void ldmx4(uint32_t& r0, uint32_t& r1, uint32_t& r2,
                                      uint32_t& r3, uint32_t addr) {
    asm volatile("ldmatrix.sync.aligned.m8n8.x4.shared.b16 {%0,%1,%2,%3}, [%4];"
        : "=r"(r0), "=r"(r1), "=r"(r2), "=r"(r3) : "r"(addr));
}
__device__ __forceinline__ void mma16816(float* c, const uint32_t* a,
                                         uint32_t b0, uint32_t b1) {
    asm volatile(
        "mma.sync.aligned.m16n8k16.row.col.f32.bf16.bf16.f32 "
        "{%0,%1,%2,%3}, {%4,%5,%6,%7}, {%8,%9}, {%0,%1,%2,%3};"
        : "+f"(c[0]), "+f"(c[1]), "+f"(c[2]), "+f"(c[3])
        : "r"(a[0]), "r"(a[1]), "r"(a[2]), "r"(a[3]), "r"(b0), "r"(b1));
}

// ======================= HMMA GEMM =========================================
#define BM 128
#define BN 128
#define BKE 64
#define STAGES 3
#define TILE_BYTES (128 * 128)
#define SM_A 0
#define SM_B (STAGES * TILE_BYTES)
#define DYN_SMEM (2 * STAGES * TILE_BYTES + 1024)

__device__ __forceinline__ void load_tile(
    const __nv_bfloat16* __restrict__ A, int lda,
    const __nv_bfloat16* __restrict__ Bt, int ldb,
    int Mrows, int rowBase, int colBase, int kt, int buf, uint32_t sb, int tid)
{
    const int k0 = kt * BKE;
    #pragma unroll
    for (int j = 0; j < 4; j++) {               // A tile
        int i = tid + 256 * j;
        int r = i >> 3, c = i & 7;
        uint32_t dst = sb + SM_A + buf * TILE_BYTES
                     + r * 128 + ((c * 16) ^ ((r & 7) * 16));
        bool ok = (rowBase + r) < Mrows;
        const __nv_bfloat16* src = ok ? (A + (size_t)(rowBase + r) * lda + k0 + c * 8) : A;
        CP16(dst, src, ok ? 16 : 0);
    }
    #pragma unroll
    for (int j = 0; j < 4; j++) {               // B tile
        int i = tid + 256 * j;
        int r = i >> 3, c = i & 7;
        uint32_t dst = sb + SM_B + buf * TILE_BYTES
                     + r * 128 + ((c * 16) ^ ((r & 7) * 16));
        const __nv_bfloat16* src = Bt + (size_t)(colBase + r) * ldb + k0 + c * 8;
        CP16(dst, src, 16);
    }
    asm volatile("cp.async.commit_group;" ::: "memory");
}

__global__ __launch_bounds__(256, 2) void tc_gemm(
    const __nv_bfloat16* __restrict__ A, int lda,
    const __nv_bfloat16* __restrict__ Bt, int ldb,
    const float* __restrict__ bias, float* __restrict__ C, int ldc,
    int Mrows, int nkt)
{
    extern __shared__ char dsm[];
    uint32_t sb = (smem_u32(dsm) + 1023u) & ~1023u;
    const int tid  = threadIdx.x;
    const int lane = tid & 31, w = tid >> 5;
    const int wm = w >> 1, wn = w & 1;
    const int rowBase = blockIdx.y * BM;
    const int colBase = blockIdx.x * BN;

    const uint32_t xm = (lane & 7) * 16;
    uint32_t aRow[2];
    #pragma unroll
    for (int mi = 0; mi < 2; mi++)
        aRow[mi] = (uint32_t)(wm * 32 + mi * 16 + (lane & 15)) * 128u;
    const uint32_t aCol = 16u * (lane >> 4);
    uint32_t bRow[4];
    #pragma unroll
    for (int p = 0; p < 4; p++)
        bRow[p] = (uint32_t)(wn * 64 + p * 16 + (lane & 7) + 8 * (lane >> 4)) * 128u;
    const uint32_t bCol = 16u * ((lane >> 3) & 1);

    float acc[2][8][4];
    #pragma unroll
    for (int mi = 0; mi < 2; mi++)
        #pragma unroll
        for (int ni = 0; ni < 8; ni++)
            #pragma unroll
            for (int r = 0; r < 4; r++) acc[mi][ni][r] = 0.f;

    #pragma unroll
    for (int s = 0; s < STAGES; s++)
        load_tile(A, lda, Bt, ldb, Mrows, rowBase, colBase, s, s, sb, tid);

    for (int kt = 0; kt < nkt; kt++) {
        const int buf = kt % STAGES;
        const int remain = nkt - 1 - kt;
        if (remain >= 2)      asm volatile("cp.async.wait_group 2;" ::: "memory");
        else if (remain == 1) asm volatile("cp.async.wait_group 1;" ::: "memory");
        else                  asm volatile("cp.async.wait_group 0;" ::: "memory");
        __syncthreads();

        const uint32_t baseA = sb + SM_A + buf * TILE_BYTES;
        const uint32_t baseB = sb + SM_B + buf * TILE_BYTES;
        #pragma unroll
        for (int kf = 0; kf < 4; kf++) {
            const uint32_t kb = kf * 32;
            uint32_t af[2][4], bf[8][2];
            #pragma unroll
            for (int mi = 0; mi < 2; mi++)
                ldmx4(af[mi][0], af[mi][1], af[mi][2], af[mi][3],
                      baseA + aRow[mi] + ((kb + aCol) ^ xm));
            #pragma unroll
            for (int p = 0; p < 4; p++)
                ldmx4(bf[2 * p][0], bf[2 * p][1], bf[2 * p + 1][0], bf[2 * p + 1][1],
                      baseB + bRow[p] + ((kb + bCol) ^ xm));
            #pragma unroll
            for (int mi = 0; mi < 2; mi++)
                #pragma unroll
                for (int ni = 0; ni < 8; ni++)
                    mma16816(acc[mi][ni], af[mi], bf[ni][0], bf[ni][1]);
        }
        __syncthreads();
        if (kt + STAGES < nkt)
            load_tile(A, lda, Bt, ldb, Mrows, rowBase, colBase, kt + STAGES, buf, sb, tid);
    }

    const int colW = colBase + wn * 64 + 2 * (lane & 3);
    #pragma unroll
    for (int mi = 0; mi < 2; mi++) {
        int r0 = rowBase + wm * 32 + mi * 16 + (lane >> 2);
        #pragma unroll
        for (int ni = 0; ni < 8; ni++) {
            int col = colW + ni * 8;
            float bx = 0.f, by = 0.f;
            if (bias) { bx = bias[col]; by = bias[col + 1]; }
            if (r0 < Mrows)
                *(float2*)&C[(size_t)r0 * ldc + col] =
                    make_float2(acc[mi][ni][0] + bx, acc[mi][ni][1] + by);
            if (r0 + 8 < Mrows)
                *(float2*)&C[(size_t)(r0 + 8) * ldc + col] =
                    make_float2(acc[mi][ni][2] + bx, acc[mi][ni][3] + by);
        }
    }
}

// ======================= split / transpose conversions =====================
// A'6: src [R][1024] -> dst [R][6144] = [Ah|Ah|Al|Ah|Am|Am]
__global__ __launch_bounds__(256) void split6_rows(
    const float* __restrict__ src, __nv_bfloat16* __restrict__ dst, int total)
{
    int idx = blockIdx.x * 256 + threadIdx.x;
    if (idx >= total) return;
    int r = idx >> 10, k = idx & 1023;
    float v = src[idx];
    __nv_bfloat16 h = __float2bfloat16(v);
    float r1 = v - __bfloat162float(h);
    __nv_bfloat16 m = __float2bfloat16(r1);
    __nv_bfloat16 l = __float2bfloat16(r1 - __bfloat162float(m));
    size_t o = (size_t)r * K6 + k;
    dst[o] = h;
    dst[o + 1024] = h;
    dst[o + 2048] = l;
    dst[o + 3072] = h;
    dst[o + 4096] = m;
    dst[o + 5120] = m;
}

// A'3: src [R][1024] -> dst [R][3072] = [Ah|Ah|Am]
__global__ __launch_bounds__(256) void split3_rows(
    const float* __restrict__ src, __nv_bfloat16* __restrict__ dst, int total)
{
    int idx = blockIdx.x * 256 + threadIdx.x;
    if (idx >= total) return;
    int r = idx >> 10, k = idx & 1023;
    float v = src[idx];
    __nv_bfloat16 h = __float2bfloat16(v);
    __nv_bfloat16 m = __float2bfloat16(v - __bfloat162float(h));
    size_t o = (size_t)r * KT3 + k;
    dst[o] = h;
    dst[o + 1024] = h;
    dst[o + 2048] = m;
}

// B'6: W col slice -> Bt [N][6144] = [Bh|Bm|Bh|Bl|Bh|Bm]
__global__ __launch_bounds__(256) void transpose_split6(
    const float* __restrict__ W, int ldw, __nv_bfloat16* __restrict__ Bt)
{
    __shared__ float t[32][33];
    int n0 = blockIdx.x * 32, k0 = blockIdx.y * 32;
    int tx = threadIdx.x & 31, ty = threadIdx.x >> 5;
    #pragma unroll
    for (int i = 0; i < 32; i += 8)
        t[ty + i][tx] = W[(size_t)(k0 + ty + i) * ldw + n0 + tx];
    __syncthreads();
    #pragma unroll
    for (int i = 0; i < 32; i += 8) {
        int n = n0 + ty + i, k = k0 + tx;
        float v = t[tx][ty + i];
        __nv_bfloat16 h = __float2bfloat16(v);
        float r1 = v - __bfloat162float(h);
        __nv_bfloat16 m = __float2bfloat16(r1);
        __nv_bfloat16 l = __float2bfloat16(r1 - __bfloat162float(m));
        size_t o = (size_t)n * K6 + k;
        Bt[o] = h;
        Bt[o + 1024] = m;
        Bt[o + 2048] = h;
        Bt[o + 3072] = l;
        Bt[o + 4096] = h;
        Bt[o + 5120] = m;
    }
}

// B'3: W col slice -> Bt [N][3072] = [Bh|Bm|Bh]
__global__ __launch_bounds__(256) void transpose_split3(
    const float* __restrict__ W, int ldw, __nv_bfloat16* __restrict__ Bt)
{
    __shared__ float t[32][33];
    int n0 = blockIdx.x * 32, k0 = blockIdx.y * 32;
    int tx = threadIdx.x & 31, ty = threadIdx.x >> 5;
    #pragma unroll
    for (int i = 0; i < 32; i += 8)
        t[ty + i][tx] = W[(size_t)(k0 + ty + i) * ldw + n0 + tx];
    __syncthreads();
    #pragma unroll
    for (int i = 0; i < 32; i += 8) {
        int n = n0 + ty + i, k = k0 + tx;
        float v = t[tx][ty + i];
        __nv_bfloat16 h = __float2bfloat16(v);
        __nv_bfloat16 m = __float2bfloat16(v - __bfloat162float(h));
        size_t o = (size_t)n * KT3 + k;
        Bt[o] = h;
        Bt[o + 1024] = m;
        Bt[o + 2048] = h;
    }
}

// ======================= small pipeline kernels ============================
__global__ void router_pool_kernel()
{
    int blk = blockIdx.x;
    int b = blk / MEXP, m = blk % MEXP;
    int p = m / POOLN, q = m % POOLN;
    int hs = (p * GRID) / POOLN, he = ((p + 1) * GRID + POOLN - 1) / POOLN;
    int ws = (q * GRID) / POOLN, we = ((q + 1) * GRID + POOLN - 1) / POOLN;
    float inv = 1.0f / (float)((he - hs) * (we - ws));
    for (int c = threadIdx.x; c < CDIM; c += blockDim.x) {
        float s = 0.f;
        for (int h = hs; h < he; h++)
            for (int w = ws; w < we; w++)
                s += g_qkv[((size_t)(b * NTOK + h * GRID + w)) * (3 * CDIM) + c];
        g_router[(size_t)blk * CDIM + c] = s * inv;
    }
}

__global__ __launch_bounds__(256) void logits_kernel()
{
    __shared__ float r_s[MEXP][HDIM];
    int bh = blockIdx.y;
    int b = bh / HEADS, h = bh % HEADS;
    for (int e = threadIdx.x; e < MEXP * HDIM; e += 256) {
        int m = e / HDIM, d = e % HDIM;
        r_s[m][d] = g_router[((size_t)(b * MEXP + m)) * CDIM + h * HDIM + d];
    }
    __syncthreads();
    int n = blockIdx.x * 256 + threadIdx.x;
    if (n >= NTOK) return;
    const float* base = &g_qkv[(size_t)(b * NTOK + n) * (3 * CDIM) + h * HDIM];
    float acck[MEXP], accq[MEXP];
    #pragma unroll
    for (int m = 0; m < MEXP; m++) { acck[m] = 0.f; accq[m] = 0.f; }
    for (int d = 0; d < HDIM; d++) {
        float qv = base[d];
        float kv = base[CDIM + d];
        #pragma unroll
        for (int m = 0; m < MEXP; m++) {
            float r = r_s[m][d];
            acck[m] += r * kv;
            accq[m] += r * qv;
        }
    }
    #pragma unroll
    for (int m = 0; m < MEXP; m++) {
        g_rlog[((size_t)(bh * MEXP + m)) * NTOK + n] = acck[m];
        g_gate[((size_t)(bh * NTOK + n)) * MEXP + m] = accq[m];
    }
}

__global__ __launch_bounds__(256) void softmax_topk_kernel()
{
    __shared__ float swv[8];
    __shared__ int   swi[8];
    __shared__ float selv[KSEL];
    __shared__ int   seli[KSEL];
    __shared__ float s_inv;

    int row = blockIdx.x;
    float* r = &g_rlog[(size_t)row * NTOK];
    int tid = threadIdx.x, lane = tid & 31, wid = tid >> 5;

    float vals[5];
    #pragma unroll
    for (int i = 0; i < 5; i++) {
        int n = tid + (i << 8);
        vals[i] = (n < NTOK) ? r[n] : -CUDART_INF_F;
    }

    for (int it = 0; it < KSEL; it++) {
        float bv = -CUDART_INF_F; int bi = 0x7FFFFFFF;
        #pragma unroll
        for (int i = 0; i < 5; i++) {
            int n = tid + (i << 8);
            float v = vals[i];
            if (v > bv || (v == bv && n < bi)) { bv = v; bi = n; }
        }
        #pragma unroll
        for (int off = 16; off > 0; off >>= 1) {
            float ov = __shfl_xor_sync(0xFFFFFFFFu, bv, off);
            int   oi = __shfl_xor_sync(0xFFFFFFFFu, bi, off);
            if (ov > bv || (ov == bv && oi < bi)) { bv = ov; bi = oi; }
        }
        if (lane == 0) { swv[wid] = bv; swi[wid] = bi; }
        __syncthreads();
        if (tid == 0) {
            float gv = swv[0]; int gi = swi[0];
            #pragma unroll
            for (int ww = 1; ww < 8; ww++)
                if (swv[ww] > gv || (swv[ww] == gv && swi[ww] < gi)) { gv = swv[ww]; gi = swi[ww]; }
            selv[it] = gv; seli[it] = gi;
        }
        __syncthreads();
        int sn = seli[it];
        if (tid == (sn & 255)) vals[sn >> 8] = -CUDART_INF_F;
    }

    if (tid < KSEL) g_topk[(size_t)row * KSEL + tid] = seli[tid];
    float mx = selv[0];
    for (int it = 0; it < KSEL; it++) {
        int sn = seli[it];
        if (tid == (sn & 255)) vals[sn >> 8] = selv[it];
    }

    float ev[5];
    float psum = 0.f;
    #pragma unroll
    for (int i = 0; i < 5; i++) {
        int n = tid + (i << 8);
        float e = (n < NTOK) ? __expf((vals[i] - mx) * SCALE) : 0.f;
        ev[i] = e;
        psum += e;
    }
    #pragma unroll
    for (int off = 16; off > 0; off >>= 1)
        psum += __shfl_xor_sync(0xFFFFFFFFu, psum, off);
    if (lane == 0) swv[wid] = psum;
    __syncthreads();
    if (tid == 0) {
        float s = 0.f;
        #pragma unroll
        for (int ww = 0; ww < 8; ww++) s += swv[ww];
        s_inv = 1.0f / s;
    }
    __syncthreads();
    float inv = s_inv;
    #pragma unroll
    for (int i = 0; i < 5; i++) {
        int n = tid + (i << 8);
        if (n < NTOK) r[n] = ev[i] * inv;
    }
}

__global__ __launch_bounds__(256) void agent_value_kernel()
{
    __shared__ float p_s[MEXP][32];
    __shared__ float v_s[32][HDIM];
    int bh = blockIdx.x;
    int b = bh / HEADS, h = bh % HEADS;
    int tid = threadIdx.x;

    float acc[7];
    #pragma unroll
    for (int i = 0; i < 7; i++) acc[i] = 0.f;

    for (int t0 = 0; t0 < NTOK; t0 += 32) {
        for (int e = tid; e < MEXP * 32; e += 256) {
            int m = e / 32, n = e % 32;
            p_s[m][n] = (t0 + n < NTOK)
                ? g_rlog[((size_t)(bh * MEXP + m)) * NTOK + t0 + n] : 0.f;
        }
        for (int e = tid; e < 32 * HDIM; e += 256) {
            int n = e / HDIM, d = e % HDIM;
            v_s[n][d] = (t0 + n < NTOK)
                ? g_qkv[(size_t)(b * NTOK + t0 + n) * (3 * CDIM) + 2 * CDIM + h * HDIM + d]
                : 0.f;
        }
        __syncthreads();
        for (int n = 0; n < 32; n++) {
            #pragma unroll
            for (int i = 0; i < 7; i++) {
                int pidx = tid + 256 * i;
                if (pidx < MEXP * HDIM) {
                    int m = pidx >> 6, d = pidx & 63;
                    acc[i] += p_s[m][n] * v_s[n][d];
                }
            }
        }
        __syncthreads();
    }
    #pragma unroll
    for (int i = 0; i < 7; i++) {
        int pidx = tid + 256 * i;
        if (pidx < MEXP * HDIM)
            g_agentv[(size_t)bh * MEXP * HDIM + pidx] = acc[i];
    }
}

#define TQ 16
__global__ __launch_bounds__(256) void attn_kernel()
{
    __shared__ float ag_s[MEXP][HDIM];
    __shared__ float q_s[TQ][HDIM];
    __shared__ float w_s[TQ][65];
    __shared__ int   sel_s[TQ][KSEL];

    int bh = blockIdx.y;
    int b = bh / HEADS, h = bh % HEADS;
    int n0 = blockIdx.x * TQ;
    int tid = threadIdx.x;

    for (int e = tid; e < MEXP * HDIM; e += 256)
        ((float*)ag_s)[e] = g_agentv[(size_t)bh * MEXP * HDIM + e];
    for (int e = tid; e < TQ * HDIM; e += 256) {
        int qi = e / HDIM, d = e % HDIM;
        int n = n0 + qi;
        q_s[qi][d] = (n < NTOK)
            ? g_qkv[(size_t)(b * NTOK + n) * (3 * CDIM) + h * HDIM + d] : 0.f;
    }
    __syncthreads();

    if (tid < TQ && n0 + tid < NTOK) {
        const float* g = &g_gate[((size_t)(bh * NTOK + n0 + tid)) * MEXP];
        float best = -CUDART_INF_F; int ei = 0;
        #pragma unroll
        for (int m = 0; m < MEXP; m++) {
            float v = g[m];
            w_s[tid][m] = v * SCALE;
            if (v > best) { best = v; ei = m; }
        }
        const int* tk = &g_topk[((size_t)(bh * MEXP + ei)) * KSEL];
        #pragma unroll
        for (int k = 0; k < KSEL; k++) sel_s[tid][k] = tk[k];
    }
    __syncthreads();

    int warp = tid >> 5, lane = tid & 31;
    for (int task = warp; task < TQ * KSEL; task += 8) {
        int qi = task / KSEL, k = task % KSEL;
        if (n0 + qi < NTOK) {
            int key = sel_s[qi][k];
            const float2* kp = (const float2*)
                &g_qkv[(size_t)(b * NTOK + key) * (3 * CDIM) + CDIM + h * HDIM];
            float2 kv = kp[lane];
            float2 qv = *(const float2*)&q_s[qi][2 * lane];
            float s = qv.x * kv.x + qv.y * kv.y;
            #pragma unroll
            for (int off = 16; off > 0; off >>= 1)
                s += __shfl_xor_sync(0xFFFFFFFFu, s, off);
            if (lane == 0) w_s[qi][MEXP + k] = s * SCALE;
        }
    }
    __syncthreads();

    if (tid < TQ && n0 + tid < NTOK) {
        float mx = -CUDART_INF_F;
        #pragma unroll
        for (int j = 0; j < MEXP + KSEL; j++) mx = fmaxf(mx, w_s[tid][j]);
        float sum = 0.f;
        #pragma unroll
        for (int j = 0; j < MEXP + KSEL; j++) {
            float e = __expf(w_s[tid][j] - mx);
            w_s[tid][j] = e;
            sum += e;
        }
        float inv = 1.0f / sum;
        #pragma unroll
        for (int j = 0; j < MEXP + KSEL; j++) w_s[tid][j] *= inv;
    }
    __syncthreads();

    int d = tid & 63;
    #pragma unroll
    for (int i = 0; i < 4; i++) {
        int qi = (tid >> 6) + i * 4;
        int n = n0 + qi;
        if (n < NTOK) {
            float o = 0.f;
            #pragma unroll
            for (int m = 0; m < MEXP; m++) o += w_s[qi][m] * ag_s[m][d];
            #pragma unroll
            for (int k = 0; k < KSEL; k++) {
                int key = sel_s[qi][k];
                o += w_s[qi][MEXP + k] *
                     g_qkv[(size_t)(b * NTOK + key) * (3 * CDIM) + 2 * CDIM + h * HDIM + d];
            }
            g_attn[(size_t)(b * NTOK + n) * CDIM + h * HDIM + d] = o;
        }
    }
}

// ---------------------------------------------------------------------------
extern "C" void kernel_launch(void* const* d_in, const int* in_sizes, int n_in,
                              void* d_out, int out_size)
{
    const float* x     = (const float*)d_in[0];
    const float* Wqkv  = (const float*)d_in[1];
    const float* Wproj = (const float*)d_in[2];
    const float* bproj = (const float*)d_in[3];
    float* out = (float*)d_out;

    float* qkv;   cudaGetSymbolAddress((void**)&qkv,   g_qkv);
    float* attn;  cudaGetSymbolAddress((void**)&attn,  g_attn);
    __nv_bfloat16* a6;   cudaGetSymbolAddress((void**)&a6,   g_a6);
    __nv_bfloat16* b6qk; cudaGetSymbolAddress((void**)&b6qk, g_b6qk);
    __nv_bfloat16* b3v;  cudaGetSymbolAddress((void**)&b3v,  g_b3v);
    __nv_bfloat16* b3p;  cudaGetSymbolAddress((void**)&b3p,  g_b3p);

    cudaFuncSetAttribute(tc_gemm, cudaFuncAttributeMaxDynamicSharedMemorySize, DYN_SMEM);

    // --- conversions for GEMM1 ---
    split6_rows<<<(MROWS * CDIM + 255) / 256, 256>>>(x, a6, MROWS * CDIM);
    {
        dim3 g(2 * CDIM / 32, CDIM / 32);
        transpose_split6<<<g, 256>>>(Wqkv, 3 * CDIM, b6qk);           // q,k columns
    }
    {
        dim3 g(CDIM / 32, CDIM / 32);
        transpose_split3<<<g, 256>>>(Wqkv + 2 * CDIM, 3 * CDIM, b3v); // v columns
    }
    // --- GEMM1a (q,k): bf16x6 ---
    {
        dim3 grid(2 * CDIM / BN, (MROWS + BM - 1) / BM);   // (16, 65)
        tc_gemm<<<grid, 256, DYN_SMEM>>>(a6, K6, b6qk, K6, nullptr,
                                         qkv, 3 * CDIM, MROWS, K6 / BKE);
    }
    // --- GEMM1b (v): bf16x3 with a PROPER A'3 = [Ah|Ah|Am] (overwrites a6;
    //     safe: stream-ordered after GEMM1a) ---
    split3_rows<<<(MROWS * CDIM + 255) / 256, 256>>>(x, a6, MROWS * CDIM);
    {
        dim3 grid(CDIM / BN, (MROWS + BM - 1) / BM);       // (8, 65)
        tc_gemm<<<grid, 256, DYN_SMEM>>>(a6, KT3, b3v, KT3, nullptr,
                                         qkv + 2 * CDIM, 3 * CDIM, MROWS, KT3 / BKE);
    }
    router_pool_kernel<<<BATCH * MEXP, 256>>>();
    {
        dim3 grid((NTOK + 255) / 256, BH);
        logits_kernel<<<grid, 256>>>();
    }
    softmax_topk_kernel<<<BH * MEXP, 256>>>();
    agent_value_kernel<<<BH, 256>>>();
    {
        dim3 grid((NTOK + TQ - 1) / TQ, BH);
        attn_kernel<<<grid, 256>>>();
    }
    // --- GEMM2: out = attn @ Wproj + b (bf16x3) ---
    split3_rows<<<(MROWS * CDIM + 255) / 256, 256>>>(attn, a6, MROWS * CDIM);
    {
        dim3 g(CDIM / 32, CDIM / 32);
        transpose_split3<<<g, 256>>>(Wproj, CDIM, b3p);
    }
    {
        dim3 grid(CDIM / BN, (MROWS + BM - 1) / BM);       // (8, 65)
        tc_gemm<<<grid, 256, DYN_SMEM>>>(a6, KT3, b3p, KT3, bproj,
                                         out, CDIM, MROWS, KT3 / BKE);
    }
}